// round 17
// baseline (speedup 1.0000x reference)
#include <cuda_runtime.h>
#include <cuda_fp16.h>
#include <cstdint>

#define NUM_HEADS 8
#define D_MODEL   512
#define DK        64
#define SEQ       2048
#define BATCH     4
#define MT        (BATCH * SEQ)        // 8192
#define BH        (BATCH * NUM_HEADS)  // 32

// ============================================================================
// Scratch (device globals — no allocation allowed)
// ============================================================================
__device__ __align__(16) __half g_Ah[3 * MT * D_MODEL];
__device__ __align__(16) __half g_Wth[4 * D_MODEL * D_MODEL];
__device__ __align__(16) __half g_Qh[BH * SEQ * DK];
__device__ __align__(16) __half g_Kh[BH * SEQ * DK];
__device__ __align__(16) __half g_Vh[BH * SEQ * DK];
__device__ int g_idx[BATCH * SEQ];
__device__ int g_nk[BATCH];

// 0.125 (1/sqrt(d_k)) * log2(e): folded into Q projection so S is in log2 units
#define QSCALE 0.18033688011117128f

// ============================================================================
// PTX primitives (all legal at compute_103 baseline)
// ============================================================================
__device__ __forceinline__ uint32_t smem_to_u32(const void* p) {
    uint32_t a;
    asm("{ .reg .u64 t; cvta.to.shared.u64 t, %1; cvt.u32.u64 %0, t; }"
        : "=r"(a) : "l"(p));
    return a;
}

__device__ __forceinline__ void ldsm4(uint32_t* r, uint32_t addr) {
    asm volatile("ldmatrix.sync.aligned.m8n8.x4.shared.b16 {%0,%1,%2,%3}, [%4];"
                 : "=r"(r[0]), "=r"(r[1]), "=r"(r[2]), "=r"(r[3]) : "r"(addr));
}

// transposing variant — B operand directly from row-major [k][n] storage
__device__ __forceinline__ void ldsm4t(uint32_t* r, uint32_t addr) {
    asm volatile("ldmatrix.sync.aligned.m8n8.x4.trans.shared.b16 {%0,%1,%2,%3}, [%4];"
                 : "=r"(r[0]), "=r"(r[1]), "=r"(r[2]), "=r"(r[3]) : "r"(addr));
}

// f16 inputs, f32 accumulate
__device__ __forceinline__ void mma_f32h(float* c, const uint32_t* a,
                                         const uint32_t* b) {
    asm volatile(
        "mma.sync.aligned.m16n8k16.row.col.f32.f16.f16.f32 "
        "{%0,%1,%2,%3}, {%4,%5,%6,%7}, {%8,%9}, {%0,%1,%2,%3};"
        : "+f"(c[0]), "+f"(c[1]), "+f"(c[2]), "+f"(c[3])
        : "r"(a[0]), "r"(a[1]), "r"(a[2]), "r"(a[3]), "r"(b[0]), "r"(b[1]));
}

#define CP16(dst, src) \
    asm volatile("cp.async.cg.shared.global [%0], [%1], 16;" \
                 :: "r"(dst), "l"(src) : "memory")
#define CP_COMMIT() asm volatile("cp.async.commit_group;" ::: "memory")
#define CP_WAIT0()  asm volatile("cp.async.wait_group 0;" ::: "memory")

// exp2 via magic-constant round + degree-4 poly on [-0.5, 0.5]; t <= 0.
__device__ __forceinline__ float fexp2m(float t) {
    t = fmaxf(t, -126.0f);
    float z = t + 12582912.0f;
    float f = t - (z - 12582912.0f);
    float p = fmaf(f, 0.0096181291f, 0.0555041087f);
    p = fmaf(p, f, 0.2402265069f);
    p = fmaf(p, f, 0.6931471806f);
    p = fmaf(p, f, 1.0f);
    uint32_t sb = (uint32_t)((__float_as_int(z) + 127) << 23);
    return __int_as_float(sb) * p;
}

// ============================================================================
// Mask prefix scan
// ============================================================================
__global__ __launch_bounds__(1024) void mask_scan_kernel(
    const int* __restrict__ mask, int* __restrict__ idx, int* __restrict__ nk) {
    const int b = blockIdx.x, tid = threadIdx.x;
    const int lane = tid & 31, w = tid >> 5;
    const int* mp = mask + b * SEQ;
    int e0 = (mp[2 * tid] != 0), e1 = (mp[2 * tid + 1] != 0);
    int tsum = e0 + e1;
    int v = tsum;
#pragma unroll
    for (int o = 1; o < 32; o <<= 1) {
        int u = __shfl_up_sync(0xffffffffu, v, o);
        if (lane >= o) v += u;
    }
    __shared__ int ws[32];
    if (lane == 31) ws[w] = v;
    __syncthreads();
    if (w == 0) {
        int x = ws[lane];
#pragma unroll
        for (int o = 1; o < 32; o <<= 1) {
            int u = __shfl_up_sync(0xffffffffu, x, o);
            if (lane >= o) x += u;
        }
        ws[lane] = x;
    }
    __syncthreads();
    int base = ((w > 0) ? ws[w - 1] : 0) + (v - tsum);
    if (e0) idx[b * SEQ + base] = 2 * tid;
    if (e1) idx[b * SEQ + base + e0] = 2 * tid + 1;
    if (tid == 0) nk[b] = ws[31];
}

// ============================================================================
// Prep kernels
// ============================================================================
__global__ void conv_b_kernel(const float4* __restrict__ q,
                              const float4* __restrict__ k,
                              const float4* __restrict__ v,
                              __half* __restrict__ Ah, int n4) {
    int i = blockIdx.x * blockDim.x + threadIdx.x;
    if (i >= n4) return;
    int z = blockIdx.y;
    const float4* in = (z == 0) ? q : (z == 1) ? k : v;
    __half2* hi = (__half2*)(Ah + (size_t)z * MT * D_MODEL);
    float4 vv = in[i];
    hi[2 * i]     = __floats2half2_rn(vv.x, vv.y);
    hi[2 * i + 1] = __floats2half2_rn(vv.z, vv.w);
}

__global__ void wt_split_b_kernel(const float* __restrict__ W0,
                                  const float* __restrict__ W1,
                                  const float* __restrict__ W2,
                                  const float* __restrict__ W3,
                                  __half* __restrict__ Wth) {
    __shared__ float ts[32][33];
    int z = blockIdx.z;
    const float* W = (z == 0) ? W0 : (z == 1) ? W1 : (z == 2) ? W2 : W3;
    __half* oh = Wth + (size_t)z * D_MODEL * D_MODEL;
    int n0 = blockIdx.x * 32, k0 = blockIdx.y * 32;
    ts[threadIdx.y][threadIdx.x] = W[(size_t)(k0 + threadIdx.y) * 512 + n0 + threadIdx.x];
    __syncthreads();
    int n = n0 + threadIdx.y, k = k0 + threadIdx.x;
    oh[(size_t)n * 512 + k] = __float2half_rn(ts[threadIdx.x][threadIdx.y]);
}

// ============================================================================
// HMMA GEMM (cp.async double-buffered), f16, f32-acc, single pass: Ah·Bh.
// BK=64. z: 0=Q (QSCALE, f16 head-split), 1=K (f16 head-split),
// 2=V (f16 head-split), 3=out proj (f32 row-major to d_out).
// ============================================================================
#define GRB    144     // smem row bytes (64 halves + 16B pad)
#define GTILE  (128 * GRB)      // 18432
#define GSTAGE (2 * GTILE)      // A + B
#define G_SMEM (2 * GSTAGE)     // 73728 — 2 CTAs/SM

__global__ __launch_bounds__(256, 2) void mm_gemm(
    const __half* __restrict__ Ahb, const __half* __restrict__ Wthb,
    const float* __restrict__ bq, const float* __restrict__ bk,
    const float* __restrict__ bv, const float* __restrict__ bo,
    __half* __restrict__ Qh, __half* __restrict__ Kh, __half* __restrict__ Vh,
    float* __restrict__ dout, int zofs) {
    extern __shared__ __align__(16) char smg[];
    const int tid = threadIdx.x, wid = tid >> 5, lane = tid & 31;
    const int wm = wid >> 1, wn = wid & 1;
    const int gr = lane >> 2, gc = lane & 3;
    const int m0 = blockIdx.y * 128, n0 = blockIdx.x * 128;
    const int z = blockIdx.z + zofs;

    const __half* Ah = Ahb + (size_t)((z == 3) ? 0 : z) * MT * D_MODEL;
    const __half* Bh = Wthb + (size_t)z * D_MODEL * D_MODEL;
    const float* bias = (z == 0) ? bq : (z == 1) ? bk : (z == 2) ? bv : bo;

    const uint32_t sb = smem_to_u32(smg);
    const uint32_t rAh = (uint32_t)(wm * 32 + (lane & 15)) * GRB + (((lane >> 4) & 1) << 4);
    const uint32_t rBh = GTILE +
        (uint32_t)(wn * 64 + (lane & 7) + (((lane >> 4) & 1) << 3)) * GRB +
        (((lane >> 3) & 1) << 4);

    const int pr = tid >> 3, pj = tid & 7;

    float c[2][8][4];
#pragma unroll
    for (int i = 0; i < 2; i++)
#pragma unroll
        for (int j = 0; j < 8; j++)
#pragma unroll
            for (int e = 0; e < 4; e++) c[i][j][e] = 0.0f;

    {
#pragma unroll
        for (int t = 0; t < 4; t++) {
            int r = pr + t * 32;
            uint32_t d = sb + (uint32_t)r * GRB + pj * 16;
            CP16(d, Ah + (size_t)(m0 + r) * 512 + pj * 8);
            CP16(d + GTILE, Bh + (size_t)(n0 + r) * 512 + pj * 8);
        }
        CP_COMMIT();
    }

    for (int kc = 0; kc < 8; kc++) {
        const uint32_t stg = sb + (uint32_t)(kc & 1) * GSTAGE;
        CP_WAIT0();
        __syncthreads();
        if (kc < 7) {
            const int k0 = (kc + 1) * 64;
            const uint32_t nstg = sb + (uint32_t)((kc + 1) & 1) * GSTAGE;
#pragma unroll
            for (int t = 0; t < 4; t++) {
                int r = pr + t * 32;
                uint32_t d = nstg + (uint32_t)r * GRB + pj * 16;
                CP16(d, Ah + (size_t)(m0 + r) * 512 + k0 + pj * 8);
                CP16(d + GTILE, Bh + (size_t)(n0 + r) * 512 + k0 + pj * 8);
            }
            CP_COMMIT();
        }

        const uint32_t aAh = stg + rAh, aBh = stg + rBh;
#pragma unroll
        for (int ks = 0; ks < 4; ks++) {
            uint32_t ah[2][4], bfr[4][4];
            ldsm4(ah[0], aAh + ks * 32);
            ldsm4(ah[1], aAh + 16 * GRB + ks * 32);
#pragma unroll
            for (int nt2 = 0; nt2 < 4; nt2++)
                ldsm4(bfr[nt2], aBh + nt2 * 16 * GRB + ks * 32);
#pragma unroll
            for (int nt2 = 0; nt2 < 4; nt2++)
#pragma unroll
                for (int q = 0; q < 2; q++)
#pragma unroll
                    for (int mt = 0; mt < 2; mt++)
                        mma_f32h(c[mt][nt2 * 2 + q], ah[mt], &bfr[nt2][q * 2]);
        }
    }

    // Epilogue
#pragma unroll
    for (int mt = 0; mt < 2; mt++) {
#pragma unroll
        for (int half_ = 0; half_ < 2; half_++) {
            int m = m0 + wm * 32 + mt * 16 + gr + half_ * 8;
            int bb = m >> 11, l = m & 2047;
#pragma unroll
            for (int nt = 0; nt < 8; nt++) {
                int n = n0 + wn * 64 + nt * 8 + 2 * gc;
                float v0 = c[mt][nt][half_ * 2 + 0] + bias[n];
                float v1 = c[mt][nt][half_ * 2 + 1] + bias[n + 1];
                if (z == 3) {
                    *(float2*)(dout + (size_t)m * 512 + n) = make_float2(v0, v1);
                } else {
                    if (z == 0) { v0 *= QSCALE; v1 *= QSCALE; }
                    int h = n >> 6, d = n & 63;
                    size_t o = ((size_t)(bb * 8 + h) * SEQ + l) * DK + d;
                    __half* oh = (z == 0) ? Qh : (z == 1) ? Kh : Vh;
                    *(__half2*)(oh + o) = __floats2half2_rn(v0, v1);
                }
            }
        }
    }
}

// ============================================================================
// HMMA flash attention, KV tile = 128 (two 64-col softmax sub-steps per
// iteration — identical update sequence to the 64-tile version, half the
// barrier/prefetch overhead). Q fragments hoisted to registers (staged once
// via stage-1 smem). K/V row-indirect through idx. V transposed in-register.
// Single-pass f16 mmas, f32 acc. 2 CTAs/SM; log2-domain scores.
// ============================================================================
#define ARB   144                 // smem row bytes (72 halves)
#define ASTG  (256 * ARB)         // one stage: K rows 0-127, V rows 128-255
#define A_SMEM (2 * ASTG)         // 73728 bytes

__global__ __launch_bounds__(256, 2) void mm_attn(
    const __half* __restrict__ Qh, const __half* __restrict__ Kh,
    const __half* __restrict__ Vh, const int* __restrict__ idx,
    const int* __restrict__ nkp, __half* __restrict__ OutH) {
    extern __shared__ __align__(16) char smA[];

    const int tid = threadIdx.x, wid = tid >> 5, lane = tid & 31;
    const int gr = lane >> 2, gc = lane & 3;
    const int q0 = blockIdx.x * 128;
    const int bh = blockIdx.y, b = bh >> 3, h = bh & 7;
    const int nk = nkp[b];
    const int niter = (nk + 127) >> 7;
    const int* idxb = idx + b * SEQ;

    const __half* Qhp = Qh + (size_t)bh * SEQ * DK;
    const __half* Khp = Kh + (size_t)bh * SEQ * DK;
    const __half* Vhp = Vh + (size_t)bh * SEQ * DK;

    const uint32_t sb = smem_to_u32(smA);
    const int pr = tid >> 3, pj = tid & 7;

    // ---- prefetch KV tile 0 into stage 0 (256 rows: K 0-127, V 128-255)
    if (niter > 0) {
#pragma unroll
        for (int t = 0; t < 8; t++) {
            int r = pr + t * 32;
            uint32_t d = sb + (uint32_t)r * ARB + pj * 16;
            int rl = r & 127;
            int jj = (rl < nk) ? rl : (nk - 1);
            int row = idxb[jj];
            const __half* src = (r < 128) ? Khp : Vhp;
            CP16(d, src + (size_t)row * DK + pj * 8);
        }
        CP_COMMIT();
    }

    // ---- stage Q through stage-1 smem, hoist fragments to registers
#pragma unroll
    for (int t = 0; t < 2; t++) {
        int i = tid + t * 256;
        int r = i >> 2, j = i & 3;
        char* dst = smA + ASTG + (size_t)r * ARB + j * 32;
        const __half* src = Qhp + (size_t)(q0 + r) * DK + j * 16;
        *(uint4*)dst = *(const uint4*)src;
        *(uint4*)(dst + 16) = *(const uint4*)(src + 8);
    }
    __syncthreads();
    uint32_t qf[4][4];
    {
        const uint32_t aQ = sb + ASTG +
            (uint32_t)(wid * 16 + (lane & 15)) * ARB + (((lane >> 4) & 1) << 4);
#pragma unroll
        for (int ks = 0; ks < 4; ks++) ldsm4(qf[ks], aQ + ks * 32);
    }
    CP_WAIT0();
    __syncthreads();   // Q frags read everywhere; tile 0 visible; stage 1 free

    // K (B operand, non-trans; storage [n=kv][k=dk])
    const uint32_t bro = (uint32_t)((lane & 7) + (((lane >> 4) & 1) << 3)) * ARB +
                         (((lane >> 3) & 1) << 4);
    // V (B operand, trans; storage [k=kv][n=dk])
    const uint32_t vro = (uint32_t)((lane & 7) + (((lane >> 3) & 1) << 3)) * ARB +
                         (((lane >> 4) & 1) << 4);

    float m0_ = -1e30f, m1_ = -1e30f, l0_ = 0.0f, l1_ = 0.0f;
    float o[8][4];
#pragma unroll
    for (int j = 0; j < 8; j++)
#pragma unroll
        for (int e = 0; e < 4; e++) o[j][e] = 0.0f;

    for (int it = 0; it < niter; it++) {
        const int cur = it & 1;
        const uint32_t stg = sb + (uint32_t)cur * ASTG;
        const int kt = it * 128;

        if (it + 1 < niter) {
            const int ktn = kt + 128;
            const uint32_t nstg = sb + (uint32_t)(1 - cur) * ASTG;
#pragma unroll
            for (int t = 0; t < 8; t++) {
                int r = pr + t * 32;
                uint32_t d = nstg + (uint32_t)r * ARB + pj * 16;
                int jj = ktn + (r & 127);
                jj = (jj < nk) ? jj : (nk - 1);
                int row = idxb[jj];
                const __half* src = (r < 128) ? Khp : Vhp;
                CP16(d, src + (size_t)row * DK + pj * 8);
            }
            CP_COMMIT();
        }

        // ==== two 64-column softmax sub-steps over this 128-row tile
#pragma unroll
        for (int hf = 0; hf < 2; hf++) {
            const int kth = kt + hf * 64;

            // ---- S = Qh·Kh (f32 acc; log2 units)
            float s[8][4];
#pragma unroll
            for (int j = 0; j < 8; j++)
#pragma unroll
                for (int e = 0; e < 4; e++) s[j][e] = 0.0f;
            const uint32_t aKh = stg + (uint32_t)(hf * 64) * ARB + bro;
#pragma unroll
            for (int ks = 0; ks < 4; ks++) {
                uint32_t kf[4][4];
#pragma unroll
                for (int nt2 = 0; nt2 < 4; nt2++)
                    ldsm4(kf[nt2], aKh + nt2 * 16 * ARB + ks * 32);
#pragma unroll
                for (int nt2 = 0; nt2 < 4; nt2++)
#pragma unroll
                    for (int q = 0; q < 2; q++)
                        mma_f32h(s[nt2 * 2 + q], qf[ks], &kf[nt2][q * 2]);
            }

            // ---- tail masking (uniform branch; kills clamped duplicates)
            if (kth + 64 > nk) {
#pragma unroll
                for (int nt = 0; nt < 8; nt++) {
                    int cb = kth + nt * 8 + 2 * gc;
                    if (cb >= nk)     { s[nt][0] = -3.0e38f; s[nt][2] = -3.0e38f; }
                    if (cb + 1 >= nk) { s[nt][1] = -3.0e38f; s[nt][3] = -3.0e38f; }
                }
            }

            // ---- row max (log2 domain)
            float mx0 = -3.0e38f, mx1 = -3.0e38f;
#pragma unroll
            for (int nt = 0; nt < 8; nt++) {
                mx0 = fmaxf(mx0, fmaxf(s[nt][0], s[nt][1]));
                mx1 = fmaxf(mx1, fmaxf(s[nt][2], s[nt][3]));
            }
            mx0 = fmaxf(mx0, __shfl_xor_sync(0xffffffffu, mx0, 1));
            mx0 = fmaxf(mx0, __shfl_xor_sync(0xffffffffu, mx0, 2));
            mx1 = fmaxf(mx1, __shfl_xor_sync(0xffffffffu, mx1, 1));
            mx1 = fmaxf(mx1, __shfl_xor_sync(0xffffffffu, mx1, 2));
            float mn0 = fmaxf(m0_, mx0), mn1 = fmaxf(m1_, mx1);
            float al0 = fexp2m(m0_ - mn0), al1 = fexp2m(m1_ - mn1);
            m0_ = mn0;
            m1_ = mn1;

            // rescale O before accumulating this sub-tile
#pragma unroll
            for (int j = 0; j < 8; j++) {
                o[j][0] *= al0;
                o[j][1] *= al0;
                o[j][2] *= al1;
                o[j][3] *= al1;
            }

            // ---- per-kp interleave: exp+pack(8) -> trans-ldsm V -> 8 PV mmas
            const uint32_t aVh = stg + (uint32_t)(128 + hf * 64) * ARB + vro;
            float sm0 = 0.0f, sm1 = 0.0f;
#pragma unroll
            for (int kp = 0; kp < 4; kp++) {
                uint32_t pa[4];
#pragma unroll
                for (int q = 0; q < 2; q++) {
                    int nt = kp * 2 + q;
                    float p0 = fexp2m(s[nt][0] - mn0);
                    float p1 = fexp2m(s[nt][1] - mn0);
                    float p2 = fexp2m(s[nt][2] - mn1);
                    float p3 = fexp2m(s[nt][3] - mn1);
                    sm0 += p0 + p1;
                    sm1 += p2 + p3;
                    __half2 hb01 = __floats2half2_rn(p0, p1);
                    __half2 hb23 = __floats2half2_rn(p2, p3);
                    pa[q * 2 + 0] = *(uint32_t*)&hb01;
                    pa[q * 2 + 1] = *(uint32_t*)&hb23;
                }
                uint32_t vf[4][4];
#pragma unroll
                for (int nt2 = 0; nt2 < 4; nt2++)
                    ldsm4t(vf[nt2], aVh + kp * 16 * ARB + nt2 * 32);
#pragma unroll
                for (int nt2 = 0; nt2 < 4; nt2++)
#pragma unroll
                    for (int q = 0; q < 2; q++)
                        mma_f32h(o[nt2 * 2 + q], pa, &vf[nt2][q * 2]);
            }
            sm0 += __shfl_xor_sync(0xffffffffu, sm0, 1);
            sm0 += __shfl_xor_sync(0xffffffffu, sm0, 2);
            sm1 += __shfl_xor_sync(0xffffffffu, sm1, 1);
            sm1 += __shfl_xor_sync(0xffffffffu, sm1, 2);
            l0_ = l0_ * al0 + sm0;
            l1_ = l1_ * al1 + sm1;
        }

        if (it + 1 < niter) {
            CP_WAIT0();
            __syncthreads();
        }
    }

    // ---- normalize + store f16 at (B, L, H*64) for out-proj
    float inv0 = (l0_ > 0.0f) ? 1.0f / l0_ : 0.0f;
    float inv1 = (l1_ > 0.0f) ? 1.0f / l1_ : 0.0f;
    int r0 = q0 + wid * 16 + gr, r1 = r0 + 8;
    size_t base0 = (size_t)(b * SEQ + r0) * D_MODEL + h * DK;
    size_t base1 = (size_t)(b * SEQ + r1) * D_MODEL + h * DK;
#pragma unroll
    for (int nt = 0; nt < 8; nt++) {
        int cl = nt * 8 + 2 * gc;
        *(__half2*)(OutH + base0 + cl) =
            __floats2half2_rn(o[nt][0] * inv0, o[nt][1] * inv0);
        *(__half2*)(OutH + base1 + cl) =
            __floats2half2_rn(o[nt][2] * inv1, o[nt][3] * inv1);
    }
}

// ============================================================================
// Launch: 6 kernels total
// ============================================================================
extern "C" void kernel_launch(void* const* d_in, const int* in_sizes, int n_in,
                              void* d_out, int out_size) {
    const float* query = (const float*)d_in[0];
    const float* key   = (const float*)d_in[1];
    const float* value = (const float*)d_in[2];
    const int*   mask  = (const int*)d_in[3];
    const float* Wq = (const float*)d_in[4];
    const float* bq = (const float*)d_in[5];
    const float* Wk = (const float*)d_in[6];
    const float* bk = (const float*)d_in[7];
    const float* Wv = (const float*)d_in[8];
    const float* bv = (const float*)d_in[9];
    const float* Wo = (const float*)d_in[10];
    const float* bo = (const float*)d_in[11];

    __half *Ah, *Wth, *Qh, *Kh, *Vh;
    int *idx, *nk;
    cudaGetSymbolAddress((void**)&Ah, g_Ah);
    cudaGetSymbolAddress((void**)&Wth, g_Wth);
    cudaGetSymbolAddress((void**)&Qh, g_Qh);
    cudaGetSymbolAddress((void**)&Kh, g_Kh);
    cudaGetSymbolAddress((void**)&Vh, g_Vh);
    cudaGetSymbolAddress((void**)&idx, g_idx);
    cudaGetSymbolAddress((void**)&nk, g_nk);

    cudaFuncSetAttribute(mm_gemm, cudaFuncAttributeMaxDynamicSharedMemorySize,
                         G_SMEM);
    cudaFuncSetAttribute(mm_attn, cudaFuncAttributeMaxDynamicSharedMemorySize,
                         A_SMEM);

    const int N4 = MT * D_MODEL / 4;

    mask_scan_kernel<<<BATCH, 1024>>>(mask, idx, nk);
    wt_split_b_kernel<<<dim3(16, 16, 4), dim3(32, 32)>>>(Wq, Wk, Wv, Wo, Wth);
    conv_b_kernel<<<dim3(N4 / 256, 3), 256>>>((const float4*)query,
                                              (const float4*)key,
                                              (const float4*)value, Ah, N4);
    mm_gemm<<<dim3(4, 64, 3), 256, G_SMEM>>>(Ah, Wth, bq, bk, bv, bo,
                                             Qh, Kh, Vh, nullptr, 0);
    mm_attn<<<dim3(SEQ / 128, BH), 256, A_SMEM>>>(Qh, Kh, Vh, idx, nk, Ah);
    mm_gemm<<<dim3(4, 64, 1), 256, G_SMEM>>>(Ah, Wth, bq, bk, bv, bo,
                                             nullptr, nullptr, nullptr,
                                             (float*)d_out, 3);
}